// round 4
// baseline (speedup 1.0000x reference)
#include <cuda_runtime.h>

#define L      4096
#define RPB    8                 // rows per block
#define NBLK   (L / RPB)         // 512 blocks
#define NTHR   256
#define GG     (L / 4 / NTHR)    // 4 column-groups of float4 per thread per row

__device__ double g_clash = 0.0;
__device__ double g_pair  = 0.0;
__device__ double g_cnt   = 0.0;
__device__ unsigned int g_done = 0;

__device__ __forceinline__ float fsqrt_approx(float x) {
    float r;
    asm("sqrt.approx.f32 %0, %1;" : "=f"(r) : "f"(x));
    return r;
}

__device__ __forceinline__ float warp_sum(float v) {
    v += __shfl_down_sync(0xffffffffu, v, 16);
    v += __shfl_down_sync(0xffffffffu, v, 8);
    v += __shfl_down_sync(0xffffffffu, v, 4);
    v += __shfl_down_sync(0xffffffffu, v, 2);
    v += __shfl_down_sync(0xffffffffu, v, 1);
    return v;
}

__global__ void __launch_bounds__(NTHR, 4)
energy_kernel(const float* __restrict__ coords,
              const float* __restrict__ cmap,
              float* __restrict__ out)
{
    __shared__ float red[64];
    const int tid = threadIdx.x;
    const int i0  = blockIdx.x * RPB;

    // Row coordinates for this block's 8 rows (broadcast loads, L1-hot)
    float xi[RPB], yi[RPB], zi[RPB];
#pragma unroll
    for (int r = 0; r < RPB; ++r) {
        xi[r] = __ldg(coords + 3 * (i0 + r) + 0);
        yi[r] = __ldg(coords + 3 * (i0 + r) + 1);
        zi[r] = __ldg(coords + 3 * (i0 + r) + 2);
    }

    float a_clash = 0.0f;   // sum over ALL pairs of relu(3.4-d)^2 (corrected below)
    float a_pair  = 0.0f;   // sum over ALL pairs of cv*(d-9)^2   (corrected below)
    float a_cnt   = 0.0f;   // sum of contact values (exact 0/1)

    const float4* cp = (const float4*)coords;

#pragma unroll
    for (int gg = 0; gg < GG; ++gg) {
        const int g = tid + gg * NTHR;          // float4 column group: cols 4g..4g+3
        // 4 consecutive j coordinates: 12 contiguous floats = 3x LDG.128
        float4 q0 = __ldg(cp + 3 * g + 0);      // x0 y0 z0 x1
        float4 q1 = __ldg(cp + 3 * g + 1);      // y1 z1 x2 y2
        float4 q2 = __ldg(cp + 3 * g + 2);      // z2 x3 y3 z3
        float xj[4] = {q0.x, q0.w, q1.z, q2.y};
        float yj[4] = {q0.y, q1.x, q1.w, q2.z};
        float zj[4] = {q0.z, q1.y, q2.x, q2.w};
#pragma unroll
        for (int r = 0; r < RPB; ++r) {
            float4 c = __ldg((const float4*)(cmap + (size_t)(i0 + r) * L) + g);
            a_cnt += (c.x + c.y) + (c.z + c.w);
            float cv[4] = {c.x, c.y, c.z, c.w};
#pragma unroll
            for (int e = 0; e < 4; ++e) {
                float dx = xj[e] - xi[r];
                float dy = yj[e] - yi[r];
                float dz = zj[e] - zi[r];
                float d2 = fmaf(dz, dz, fmaf(dy, dy, dx * dx));
                float d  = fsqrt_approx(d2) + 1e-8f;
                float t  = fmaxf(3.4f - d, 0.0f);
                a_clash  = fmaf(t, t, a_clash);
                float u  = d - 9.0f;             // target_dist = 6.0 * 1.5
                float w  = u * cv[e];            // contact mask via multiply (cv in {0,1})
                a_pair   = fmaf(w, u, a_pair);
            }
        }
    }

    // Near-diagonal correction for this block's rows: remove |j-i| <= 2 terms
    // (same fp expressions as the main loop -> clean cancellation)
    if (tid < RPB * 5) {
        const int r = tid / 5;
        const int o = tid % 5 - 2;
        const int i = i0 + r;
        const int j = i + o;
        if (j >= 0 && j < L) {
            float xI = __ldg(coords + 3 * i + 0);
            float yI = __ldg(coords + 3 * i + 1);
            float zI = __ldg(coords + 3 * i + 2);
            float xJ = __ldg(coords + 3 * j + 0);
            float yJ = __ldg(coords + 3 * j + 1);
            float zJ = __ldg(coords + 3 * j + 2);
            float dx = xJ - xI, dy = yJ - yI, dz = zJ - zI;
            float d2 = fmaf(dz, dz, fmaf(dy, dy, dx * dx));
            float d  = fsqrt_approx(d2) + 1e-8f;
            float t  = fmaxf(3.4f - d, 0.0f);
            a_clash -= t * t;
            float cv = __ldg(cmap + (size_t)i * L + j);
            float u  = d - 9.0f;
            float w  = u * cv;
            a_pair  = fmaf(-w, u, a_pair);
        }
    }

    // Block reduction
    a_clash = warp_sum(a_clash);
    a_pair  = warp_sum(a_pair);
    a_cnt   = warp_sum(a_cnt);
    const int wid  = tid >> 5;
    const int lane = tid & 31;
    if (lane == 0) {
        red[wid]      = a_clash;
        red[8 + wid]  = a_pair;
        red[16 + wid] = a_cnt;
    }
    __syncthreads();
    if (tid == 0) {
        float cs = 0.0f, ps = 0.0f, ns = 0.0f;
        for (int w = 0; w < 8; ++w) { cs += red[w]; ps += red[8 + w]; ns += red[16 + w]; }
        atomicAdd(&g_clash, (double)cs);
        atomicAdd(&g_pair,  (double)ps);
        atomicAdd(&g_cnt,   (double)ns);
        __threadfence();
        unsigned prev = atomicAdd(&g_done, 1u);
        red[24] = (prev == (unsigned)(NBLK - 1)) ? 1.0f : 0.0f;
    }
    __syncthreads();

    // Last block: bond term + finalize + reset accumulators for next replay
    if (red[24] != 0.0f) {
        float b = 0.0f;
        for (int k = tid; k < L - 1; k += NTHR) {
            float dx = __ldg(coords + 3 * k + 3) - __ldg(coords + 3 * k + 0);
            float dy = __ldg(coords + 3 * k + 4) - __ldg(coords + 3 * k + 1);
            float dz = __ldg(coords + 3 * k + 5) - __ldg(coords + 3 * k + 2);
            float d  = fsqrt_approx(fmaf(dz, dz, fmaf(dy, dy, dx * dx)));
            float t  = d - 6.0f;               // IDEAL_C1_C1
            b = fmaf(t, t, b);
        }
        b = warp_sum(b);
        if (lane == 0) red[32 + wid] = b;
        __syncthreads();
        if (tid == 0) {
            float bs = 0.0f;
            for (int w = 0; w < 8; ++w) bs += red[32 + w];
            double e_bond  = (double)bs / (double)(L - 1);
            double e_clash = (g_clash * 0.5) / (double)L;     // halve: sym sum -> upper triangle
            double cnt     = g_cnt < 1.0 ? 1.0 : g_cnt;
            double e_pair  = g_pair / cnt;
            out[0] = (float)(e_bond + 2.0 * e_clash + 0.5 * e_pair);
            // reset for next graph replay
            g_clash = 0.0;
            g_pair  = 0.0;
            g_cnt   = 0.0;
            g_done  = 0u;
        }
    }
}

extern "C" void kernel_launch(void* const* d_in, const int* in_sizes, int n_in,
                              void* d_out, int out_size) {
    const float* a0 = (const float*)d_in[0];
    const float* a1 = (const float*)d_in[1];
    // coords is the small input (L*3), contact_map the big one (L*L)
    const float* coords = (in_sizes[0] < in_sizes[1]) ? a0 : a1;
    const float* cmap   = (in_sizes[0] < in_sizes[1]) ? a1 : a0;
    energy_kernel<<<NBLK, NTHR>>>(coords, cmap, (float*)d_out);
}